// round 15
// baseline (speedup 1.0000x reference)
#include <cuda_runtime.h>
#include <cuda_fp16.h>
#include <cstdint>

static constexpr int NN = 100000;
static constexpr int NE = 1600000;
static constexpr int D  = 128;

// ---------------- scratch (device globals; no allocations allowed) ----------
__device__ float g_h[NN * D];
__device__ float g_tmp[NN * D];
__device__ __half g_ha[NN * D];          // h as fp16 (single plane)
__device__ __half g_nba[NN * D];         // aggregated neighbors as fp16
__device__ __half g_wth[3 * D * 256];    // layer W^T hi [l][n][k]; k<128:Ws, k>=128:Wn
__device__ __half g_wtl[3 * D * 256];    // layer W^T lo
__device__ __half g_wtih[D * D];         // input W^T hi [n][k]
__device__ __half g_wtil[D * D];         // input W^T lo
__device__ float g_biasc[3 * D];
__device__ int   g_counts[NN];
__device__ int   g_offsets[NN + 1];
__device__ int   g_cursor[NN];
__device__ float g_degw[NN];
__device__ int   g_csr_src[NE];
__device__ float g_csr_w[NE];
__device__ int   g_blocksum[512];
__device__ int   g_blockpref[512];
__device__ float g_colsum[3 * D];
__device__ float g_colsumsq[3 * D];

// ---------------- helpers -------------------------------------------------------
__device__ __forceinline__ uint32_t ph2(float a, float b) {
    __half2 h = __floats2half2_rn(a, b);
    return *(uint32_t*)&h;
}
__device__ __forceinline__ void split_half(float v, __half& hi, __half& lo) {
    hi = __float2half(v);
    lo = __float2half(v - __half2float(hi));
}
__device__ __forceinline__ uint32_t smem_u32(const void* p) {
    uint32_t a;
    asm("{ .reg .u64 t; cvta.to.shared.u64 t, %1; cvt.u32.u64 %0, t; }" : "=r"(a) : "l"(p));
    return a;
}
__device__ __forceinline__ void mma16816(float* c, uint32_t a0, uint32_t a1,
                                         uint32_t a2, uint32_t a3,
                                         uint32_t b0, uint32_t b1) {
    asm volatile(
        "mma.sync.aligned.m16n8k16.row.col.f32.f16.f16.f32 "
        "{%0,%1,%2,%3}, {%4,%5,%6,%7}, {%8,%9}, {%0,%1,%2,%3};"
        : "+f"(c[0]), "+f"(c[1]), "+f"(c[2]), "+f"(c[3])
        : "r"(a0), "r"(a1), "r"(a2), "r"(a3), "r"(b0), "r"(b1));
}
__device__ __forceinline__ void ldm_x4(uint32_t* r, uint32_t addr) {
    asm volatile("ldmatrix.sync.aligned.m8n8.x4.shared.b16 {%0,%1,%2,%3}, [%4];"
                 : "=r"(r[0]), "=r"(r[1]), "=r"(r[2]), "=r"(r[3]) : "r"(addr));
}

// ---------------- zero ----------------------------------------------------------
__global__ void zero_kernel() {
    int i = blockIdx.x * blockDim.x + threadIdx.x;
    if (i < NN) { g_counts[i] = 0; g_degw[i] = 0.f; }
    if (i < 3 * D) { g_colsum[i] = 0.f; g_colsumsq[i] = 0.f; }
}

// ---------------- degree histogram ---------------------------------------------
__global__ void hist_kernel(const int* __restrict__ col, const float* __restrict__ ew) {
    int i = blockIdx.x * blockDim.x + threadIdx.x;
    if (i < NE) {
        int c = col[i];
        atomicAdd(&g_counts[c], 1);
        atomicAdd(&g_degw[c], ew[i]);
    }
}

// ---------------- 3-phase block scan -------------------------------------------
__global__ void scan1_kernel() {
    __shared__ int wsum[8];
    int tid = threadIdx.x, lane = tid & 31, wid = tid >> 5;
    int i = blockIdx.x * 256 + tid;
    int v = (i < NN) ? g_counts[i] : 0;
    int x = v;
    #pragma unroll
    for (int o = 1; o < 32; o <<= 1) {
        int t = __shfl_up_sync(0xffffffffu, x, o);
        if (lane >= o) x += t;
    }
    if (lane == 31) wsum[wid] = x;
    __syncthreads();
    if (tid < 8) {
        int s = wsum[tid];
        #pragma unroll
        for (int o = 1; o < 8; o <<= 1) {
            int t = __shfl_up_sync(0xffu, s, o, 8);
            if (tid >= o) s += t;
        }
        wsum[tid] = s;
    }
    __syncthreads();
    int excl = (wid ? wsum[wid - 1] : 0) + x - v;
    if (i < NN) g_offsets[i] = excl;
    if (tid == 255) g_blocksum[blockIdx.x] = wsum[7];
}

__global__ void scan2_kernel(int nb) {
    __shared__ int wsum[16];
    int tid = threadIdx.x, lane = tid & 31, wid = tid >> 5;
    int v = (tid < nb) ? g_blocksum[tid] : 0;
    int x = v;
    #pragma unroll
    for (int o = 1; o < 32; o <<= 1) {
        int t = __shfl_up_sync(0xffffffffu, x, o);
        if (lane >= o) x += t;
    }
    if (lane == 31) wsum[wid] = x;
    __syncthreads();
    if (tid < 16) {
        int s = wsum[tid];
        #pragma unroll
        for (int o = 1; o < 16; o <<= 1) {
            int t = __shfl_up_sync(0xffffu, s, o, 16);
            if (tid >= o) s += t;
        }
        wsum[tid] = s;
    }
    __syncthreads();
    int excl = (wid ? wsum[wid - 1] : 0) + x - v;
    if (tid < nb) g_blockpref[tid] = excl;
}

__global__ void scan3_kernel() {
    int i = blockIdx.x * blockDim.x + threadIdx.x;
    if (i < NN) {
        int off = g_offsets[i] + g_blockpref[i >> 8];
        g_offsets[i] = off;
        g_cursor[i] = off;
    }
    if (i == 0) g_offsets[NN] = NE;
}

// ---------------- CSR scatter ---------------------------------------------------
__global__ void scatter_kernel(const int* __restrict__ row, const int* __restrict__ col,
                               const float* __restrict__ ew) {
    int i = blockIdx.x * blockDim.x + threadIdx.x;
    if (i < NE) {
        int c = col[i];
        int p = atomicAdd(&g_cursor[c], 1);
        g_csr_src[p] = row[i];
        g_csr_w[p]   = ew[i];
    }
}

// ---------------- weight convert + transpose (fp16 hi/lo) -----------------------
__global__ void wconv_kernel(const float* __restrict__ Win,
                             const float* __restrict__ Ws0, const float* __restrict__ Wn0,
                             const float* __restrict__ Ws1, const float* __restrict__ Wn1,
                             const float* __restrict__ Ws2, const float* __restrict__ Wn2) {
    int i = blockIdx.x * blockDim.x + threadIdx.x;
    if (i < D * D) {
        int n = i >> 7, k = i & 127;
        float v = Win[k * D + n];
        __half h, l; split_half(v, h, l);
        g_wtih[i] = h; g_wtil[i] = l;
        return;
    }
    int j = i - D * D;
    if (j < 3 * D * 256) {
        int l = j / (D * 256), r = j % (D * 256);
        int n = r >> 8, k = r & 255;
        const float* Ws = (l == 0) ? Ws0 : (l == 1) ? Ws1 : Ws2;
        const float* Wn = (l == 0) ? Wn0 : (l == 1) ? Wn1 : Wn2;
        float v = (k < 128) ? Ws[k * D + n] : Wn[(k - 128) * D + n];
        __half h, lo; split_half(v, h, lo);
        g_wth[j] = h; g_wtl[j] = lo;
    }
}

__global__ void bias_kernel(const float* __restrict__ bs0, const float* __restrict__ bn0,
                            const float* __restrict__ bs1, const float* __restrict__ bn1,
                            const float* __restrict__ bs2, const float* __restrict__ bn2) {
    int tid = threadIdx.x;
    int l = tid >> 7, c = tid & 127;
    const float* bs = (l == 0) ? bs0 : (l == 1) ? bs1 : bs2;
    const float* bn = (l == 0) ? bn0 : (l == 1) ? bn1 : bn2;
    g_biasc[tid] = bs[c] + bn[c];
}

// ---------------- tensor-core GEMM (fp16 2-term, K=128, M-tile 256, persistent) --
// 148 blocks loop over tiles; B (both planes) staged once per block.
// bstride: row stride of Bth/Btl in halfs (256 for layer weight slices).
// ACCIN: read outF and accumulate (for the nb@Wn half of a split layer GEMM).
template <bool RELU, bool WRITE_F16, bool STATS, bool AFP32, bool ACCIN>
__global__ void __launch_bounds__(512, 1)
gemm_mma(const float* __restrict__ Ax, const __half* __restrict__ A1,
         const __half* __restrict__ Bth, const __half* __restrict__ Btl, int bstride,
         const float* __restrict__ bias,
         float* __restrict__ outF, __half* __restrict__ outH,
         float* __restrict__ statS, float* __restrict__ statQ, int M) {
    constexpr int MT    = 256;
    constexpr int BPADB = 136;
    constexpr int APAD  = 136;
    extern __shared__ char smem[];
    __half* Bs = (__half*)smem;                  // [2pl][128][BPADB]
    __half* As = Bs + 2 * 128 * BPADB;           // [MT][APAD]
    float* s_bias = (float*)(As + MT * APAD);
    float* s_sum = s_bias + 128;
    float* s_sq  = s_sum + 128;

    const int tid = threadIdx.x;
    const int lane = tid & 31, wid = tid >> 5;
    const int wm = wid >> 2, wn = wid & 3;
    const int qr = lane >> 2, qc = (lane & 3) * 2;
    const uint32_t sBs = smem_u32(Bs);
    const uint32_t sAs = smem_u32(As);
    const int ntiles = (M + MT - 1) / MT;

    if (tid < D) {
        s_bias[tid] = bias ? bias[tid] : 0.f;
        if (STATS) { s_sum[tid] = 0.f; s_sq[tid] = 0.f; }
    }

    // ---- stage B (both planes, 128x128) once per block ----
    #pragma unroll
    for (int i = tid; i < 2 * 128 * 16; i += 512) {
        int plane = i >> 11;
        int rem = i & 2047;
        int r = rem >> 4, j = rem & 15;
        const __half* src = (plane ? Btl : Bth) + r * bstride + j * 8;
        *(uint4*)(Bs + plane * 128 * BPADB + r * BPADB + j * 8) = *(const uint4*)src;
    }

    const int a_row_l = lane & 15;
    const int a_col_l = (lane >> 4) * 8;
    const int b_row_l = (lane & 7) + ((lane >> 4) << 3);
    const int b_col_l = ((lane >> 3) & 1) * 8;

    for (int tile = blockIdx.x; tile < ntiles; tile += gridDim.x) {
        const int row0 = tile * MT;
        __syncthreads();   // B visible (1st iter); As reuse safe (later iters)

        // ---- stage A (MT x 128 fp16) ----
        #pragma unroll
        for (int t = 0; t < 8; t++) {
            int u = tid + t * 512;
            int r = u >> 4, j = u & 15;
            int g = row0 + r;
            if (AFP32) {
                float4 f0 = make_float4(0.f, 0.f, 0.f, 0.f);
                float4 f1 = make_float4(0.f, 0.f, 0.f, 0.f);
                if (g < M) {
                    f0 = *(const float4*)(Ax + (size_t)g * D + j * 8);
                    f1 = *(const float4*)(Ax + (size_t)g * D + j * 8 + 4);
                }
                uint4 v = make_uint4(ph2(f0.x, f0.y), ph2(f0.z, f0.w),
                                     ph2(f1.x, f1.y), ph2(f1.z, f1.w));
                *(uint4*)(As + r * APAD + j * 8) = v;
            } else {
                uint4 v = make_uint4(0, 0, 0, 0);
                if (g < M) v = *(const uint4*)(A1 + (size_t)g * D + j * 8);
                *(uint4*)(As + r * APAD + j * 8) = v;
            }
        }
        __syncthreads();

        float acc[4][4][4];
        #pragma unroll
        for (int mi = 0; mi < 4; mi++)
            #pragma unroll
            for (int ni = 0; ni < 4; ni++)
                #pragma unroll
                for (int r = 0; r < 4; r++) acc[mi][ni][r] = 0.f;

        #pragma unroll
        for (int s = 0; s < 8; s++) {
            const int kk = s * 16;
            uint32_t ah[4][4];
            #pragma unroll
            for (int mi = 0; mi < 4; mi++) {
                uint32_t r = wm * 64 + mi * 16 + a_row_l;
                uint32_t c = kk + a_col_l;
                ldm_x4(ah[mi], sAs + (r * APAD + c) * 2);
            }
            uint32_t bh[4][2], bl[4][2];
            #pragma unroll
            for (int pp = 0; pp < 2; pp++) {
                uint32_t r = wn * 32 + pp * 16 + b_row_l;
                uint32_t c = kk + b_col_l;
                uint32_t t[4];
                ldm_x4(t, sBs + (r * BPADB + c) * 2);
                bh[pp * 2][0] = t[0]; bh[pp * 2][1] = t[1];
                bh[pp * 2 + 1][0] = t[2]; bh[pp * 2 + 1][1] = t[3];
                ldm_x4(t, sBs + (128 * BPADB + r * BPADB + c) * 2);
                bl[pp * 2][0] = t[0]; bl[pp * 2][1] = t[1];
                bl[pp * 2 + 1][0] = t[2]; bl[pp * 2 + 1][1] = t[3];
            }
            #pragma unroll
            for (int mi = 0; mi < 4; mi++) {
                #pragma unroll
                for (int ni = 0; ni < 4; ni++) {
                    mma16816(acc[mi][ni], ah[mi][0], ah[mi][1], ah[mi][2], ah[mi][3],
                             bh[ni][0], bh[ni][1]);
                    mma16816(acc[mi][ni], ah[mi][0], ah[mi][1], ah[mi][2], ah[mi][3],
                             bl[ni][0], bl[ni][1]);
                }
            }
        }

        // ---- epilogue ----
        float cs[8], cq[8];
        if (STATS) {
            #pragma unroll
            for (int j = 0; j < 8; j++) { cs[j] = 0.f; cq[j] = 0.f; }
        }

        #pragma unroll
        for (int mi = 0; mi < 4; mi++) {
            int r0 = row0 + wm * 64 + mi * 16 + qr;
            #pragma unroll
            for (int ni = 0; ni < 4; ni++) {
                int col = wn * 32 + ni * 8 + qc;
                float b0v = s_bias[col], b1v = s_bias[col + 1];
                float v00 = acc[mi][ni][0] + b0v, v01 = acc[mi][ni][1] + b1v;
                float v10 = acc[mi][ni][2] + b0v, v11 = acc[mi][ni][3] + b1v;
                if (r0 < M) {
                    float* op = outF + (size_t)r0 * D + col;
                    if (ACCIN) { float2 o = *(float2*)op; v00 += o.x; v01 += o.y; }
                    if (RELU) { v00 = fmaxf(v00, 0.f); v01 = fmaxf(v01, 0.f); }
                    *(float2*)op = make_float2(v00, v01);
                    if (STATS) {
                        cs[ni * 2] += v00; cq[ni * 2] += v00 * v00;
                        cs[ni * 2 + 1] += v01; cq[ni * 2 + 1] += v01 * v01;
                    }
                    if (WRITE_F16)
                        *(uint32_t*)(outH + (size_t)r0 * D + col) = ph2(v00, v01);
                }
                if (r0 + 8 < M) {
                    float* op = outF + (size_t)(r0 + 8) * D + col;
                    if (ACCIN) { float2 o = *(float2*)op; v10 += o.x; v11 += o.y; }
                    if (RELU) { v10 = fmaxf(v10, 0.f); v11 = fmaxf(v11, 0.f); }
                    *(float2*)op = make_float2(v10, v11);
                    if (STATS) {
                        cs[ni * 2] += v10; cq[ni * 2] += v10 * v10;
                        cs[ni * 2 + 1] += v11; cq[ni * 2 + 1] += v11 * v11;
                    }
                    if (WRITE_F16)
                        *(uint32_t*)(outH + (size_t)(r0 + 8) * D + col) = ph2(v10, v11);
                }
            }
        }

        if (STATS) {
            #pragma unroll
            for (int o = 4; o < 32; o <<= 1) {
                #pragma unroll
                for (int j = 0; j < 8; j++) {
                    cs[j] += __shfl_down_sync(0xffffffffu, cs[j], o);
                    cq[j] += __shfl_down_sync(0xffffffffu, cq[j], o);
                }
            }
            if (lane < 4) {
                #pragma unroll
                for (int ni = 0; ni < 4; ni++) {
                    int col = wn * 32 + ni * 8 + qc;
                    atomicAdd(&s_sum[col],     cs[ni * 2]);
                    atomicAdd(&s_sq[col],      cq[ni * 2]);
                    atomicAdd(&s_sum[col + 1], cs[ni * 2 + 1]);
                    atomicAdd(&s_sq[col + 1],  cq[ni * 2 + 1]);
                }
            }
        }
    }

    if (STATS) {
        __syncthreads();
        if (tid < D) {
            atomicAdd(&statS[tid], s_sum[tid]);
            atomicAdd(&statQ[tid], s_sq[tid]);
        }
    }
}

// ---------------- per-node weighted-mean aggregation (warp per node) ------------
__global__ void aggregate_kernel() {
    int warp = (blockIdx.x * blockDim.x + threadIdx.x) >> 5;
    int lane = threadIdx.x & 31;
    if (warp >= NN) return;
    int start = g_offsets[warp], end = g_offsets[warp + 1];
    float4 acc = make_float4(0.f, 0.f, 0.f, 0.f);
    for (int e = start; e < end; e += 32) {
        int idx = e + lane;
        int s = 0; float w = 0.f;
        if (idx < end) { s = g_csr_src[idx]; w = g_csr_w[idx]; }
        int cnt = min(32, end - e);
        for (int j = 0; j < cnt; j++) {
            int   sj = __shfl_sync(0xffffffffu, s, j);
            float wj = __shfl_sync(0xffffffffu, w, j);
            uint2 u = *(const uint2*)(g_ha + (size_t)sj * D + lane * 4);
            float2 f0 = __half22float2(*(__half2*)&u.x);
            float2 f1 = __half22float2(*(__half2*)&u.y);
            acc.x += f0.x * wj; acc.y += f0.y * wj;
            acc.z += f1.x * wj; acc.w += f1.y * wj;
        }
    }
    float dg = fmaxf(g_degw[warp], 1.0f);
    float inv = 1.0f / dg;
    acc.x *= inv; acc.y *= inv; acc.z *= inv; acc.w *= inv;
    *(uint2*)(g_nba + (size_t)warp * D + lane * 4) =
        make_uint2(ph2(acc.x, acc.y), ph2(acc.z, acc.w));
}

// ---------------- bn + (relu) + residual (+ fp16 plane); scale/shift inline -----
__global__ void bn_res_kernel(float* __restrict__ out, __half* __restrict__ oh,
                              int relu,
                              const float* __restrict__ csum,
                              const float* __restrict__ csumsq,
                              const float* __restrict__ gg,
                              const float* __restrict__ be) {
    __shared__ float s_scale[D], s_shift[D];
    int tid = threadIdx.x;
    if (tid < D) {
        const float invn = 1.0f / (float)NN;
        float mu  = csum[tid] * invn;
        float var = csumsq[tid] * invn - mu * mu;
        var = fmaxf(var, 0.f);
        float sc = gg[tid] * rsqrtf(var + 1e-5f);
        s_scale[tid] = sc;
        s_shift[tid] = be[tid] - mu * sc;
    }
    __syncthreads();

    int i = blockIdx.x * blockDim.x + tid;
    if (i >= NN * D / 4) return;
    int cb = (i * 4) & (D - 1);
    float4 t  = ((const float4*)g_tmp)[i];
    float4 hv = ((const float4*)g_h)[i];
    float4 v;
    v.x = t.x * s_scale[cb]     + s_shift[cb];
    v.y = t.y * s_scale[cb + 1] + s_shift[cb + 1];
    v.z = t.z * s_scale[cb + 2] + s_shift[cb + 2];
    v.w = t.w * s_scale[cb + 3] + s_shift[cb + 3];
    if (relu) {
        v.x = fmaxf(v.x, 0.f); v.y = fmaxf(v.y, 0.f);
        v.z = fmaxf(v.z, 0.f); v.w = fmaxf(v.w, 0.f);
    }
    v.x += hv.x; v.y += hv.y; v.z += hv.z; v.w += hv.w;
    ((float4*)out)[i] = v;
    if (oh) {
        *(uint2*)(oh + (size_t)i * 4) = make_uint2(ph2(v.x, v.y), ph2(v.z, v.w));
    }
}

// ---------------- side stream / events (static-init, before checkpoints) --------
static cudaStream_t s_side = nullptr;
static cudaEvent_t  g_evs[8] = {};
namespace {
struct SideInit {
    SideInit() {
        cudaStreamCreateWithFlags(&s_side, cudaStreamNonBlocking);
        for (int i = 0; i < 8; i++)
            cudaEventCreateWithFlags(&g_evs[i], cudaEventDisableTiming);
    }
};
static SideInit g_side_init;
}

// ---------------- launch ---------------------------------------------------------
extern "C" void kernel_launch(void* const* d_in, const int* in_sizes, int n_in,
                              void* d_out, int out_size) {
    const float* x    = (const float*)d_in[0];
    const int*   ei   = (const int*)d_in[1];
    const float* ew   = (const float*)d_in[2];
    const float* W_in = (const float*)d_in[3];
    const float* b_in = (const float*)d_in[4];
    const float* P[18];
    for (int i = 0; i < 18; i++) P[i] = (const float*)d_in[5 + i];
    const int* row = ei;
    const int* col = ei + NE;
    float* out = (float*)d_out;

    float *ph, *ptmp, *pbiasc, *pcs, *pcq;
    __half *pha, *pnba, *pwth, *pwtl, *pwtih, *pwtil;
    cudaGetSymbolAddress((void**)&ph,    g_h);
    cudaGetSymbolAddress((void**)&ptmp,  g_tmp);
    cudaGetSymbolAddress((void**)&pha,   g_ha);
    cudaGetSymbolAddress((void**)&pnba,  g_nba);
    cudaGetSymbolAddress((void**)&pwth,  g_wth);
    cudaGetSymbolAddress((void**)&pwtl,  g_wtl);
    cudaGetSymbolAddress((void**)&pwtih, g_wtih);
    cudaGetSymbolAddress((void**)&pwtil, g_wtil);
    cudaGetSymbolAddress((void**)&pbiasc, g_biasc);
    cudaGetSymbolAddress((void**)&pcs,   g_colsum);
    cudaGetSymbolAddress((void**)&pcq,   g_colsumsq);

    const int SMEMB = (2 * 128 * 136 + 256 * 136) * 2 + 3 * 512;   // 140800
    cudaFuncSetAttribute(gemm_mma<true,  true,  false, true,  false>,
                         cudaFuncAttributeMaxDynamicSharedMemorySize, SMEMB);
    cudaFuncSetAttribute(gemm_mma<false, false, false, false, false>,
                         cudaFuncAttributeMaxDynamicSharedMemorySize, SMEMB);
    cudaFuncSetAttribute(gemm_mma<false, false, true,  false, true>,
                         cudaFuncAttributeMaxDynamicSharedMemorySize, SMEMB);

    const int PGRID   = 148;
    const int SCAN_NB = (NN + 255) / 256;   // 391

    zero_kernel<<<(NN + 255) / 256, 256>>>();

    bool forked = (s_side != nullptr);
    for (int i = 0; i < 8 && forked; i++) if (!g_evs[i]) forked = false;
    if (forked) {
        if (cudaEventRecord(g_evs[0], 0) != cudaSuccess ||
            cudaStreamWaitEvent(s_side, g_evs[0], 0) != cudaSuccess)
            forked = false;
    }
    cudaStream_t cs = forked ? s_side : (cudaStream_t)0;

    wconv_kernel<<<(D * D + 3 * D * 256 + 255) / 256, 256>>>(
        W_in, P[0], P[2], P[6], P[8], P[12], P[14]);
    bias_kernel<<<1, 384>>>(P[1], P[3], P[7], P[9], P[13], P[15]);

    // index 3 (profiled): input GEMM, x->fp16 fused into staging
    gemm_mma<true, true, false, true, false><<<PGRID, 512, SMEMB>>>(
        x, nullptr, pwtih, pwtil, 128, b_in, ph, pha, nullptr, nullptr, NN);

    // CSR build on side stream (overlaps wconv/bias/gemm_in)
    hist_kernel<<<(NE + 255) / 256, 256, 0, cs>>>(col, ew);
    scan1_kernel<<<SCAN_NB, 256, 0, cs>>>();
    scan2_kernel<<<1, 512, 0, cs>>>(SCAN_NB);
    scan3_kernel<<<SCAN_NB, 256, 0, cs>>>();
    scatter_kernel<<<(NE + 255) / 256, 256, 0, cs>>>(row, col, ew);

    if (forked) {
        cudaEventRecord(g_evs[1], s_side);
        cudaStreamWaitEvent((cudaStream_t)0, g_evs[1], 0);
    }

    for (int l = 0; l < 3; l++) {
        const __half* Wl_h = pwth + l * D * 256;
        const __half* Wl_l = pwtl + l * D * 256;

        if (forked) {
            // fork: gemm_h (h@Ws -> tmp) on side, concurrent with aggregate
            cudaEventRecord(g_evs[2 + 2 * l], 0);
            cudaStreamWaitEvent(s_side, g_evs[2 + 2 * l], 0);
            gemm_mma<false, false, false, false, false><<<PGRID, 512, SMEMB, s_side>>>(
                nullptr, pha, Wl_h, Wl_l, 256, nullptr, ptmp, nullptr,
                nullptr, nullptr, NN);
            aggregate_kernel<<<NN / 8, 256>>>();
            cudaEventRecord(g_evs[3 + 2 * l], s_side);
            cudaStreamWaitEvent((cudaStream_t)0, g_evs[3 + 2 * l], 0);
        } else {
            gemm_mma<false, false, false, false, false><<<PGRID, 512, SMEMB>>>(
                nullptr, pha, Wl_h, Wl_l, 256, nullptr, ptmp, nullptr,
                nullptr, nullptr, NN);
            aggregate_kernel<<<NN / 8, 256>>>();
        }

        // gemm_nb: tmp += nb@Wn + bias, with BN stats
        gemm_mma<false, false, true, false, true><<<PGRID, 512, SMEMB>>>(
            nullptr, pnba, Wl_h + 128, Wl_l + 128, 256, pbiasc + l * D,
            ptmp, nullptr, pcs + l * D, pcq + l * D, NN);

        bn_res_kernel<<<(NN * D / 4 + 255) / 256, 256>>>(
            (l < 2) ? ph : out,
            (l < 2) ? pha : nullptr,
            (l < 2) ? 1 : 0,
            pcs + l * D, pcq + l * D, P[6 * l + 4], P[6 * l + 5]);
    }
}

// round 16
// speedup vs baseline: 1.1604x; 1.1604x over previous
#include <cuda_runtime.h>
#include <cuda_fp16.h>
#include <cstdint>

static constexpr int NN = 100000;
static constexpr int NE = 1600000;
static constexpr int D  = 128;

// ---------------- scratch (device globals; no allocations allowed) ----------
__device__ float g_h[NN * D];
__device__ float g_tmp[NN * D];
__device__ __half g_ha[NN * D];          // h as fp16 (single plane)
__device__ __half g_nba[NN * D];         // aggregated neighbors as fp16
__device__ __half g_wth[3 * D * 256];    // layer W^T hi [l][n][k]; k<128:Ws, k>=128:Wn
__device__ __half g_wtl[3 * D * 256];    // layer W^T lo
__device__ __half g_wtih[D * D];         // input W^T hi [n][k]
__device__ __half g_wtil[D * D];         // input W^T lo
__device__ float g_biasc[3 * D];
__device__ int   g_counts[NN];
__device__ int   g_offsets[NN + 1];
__device__ int   g_cursor[NN];
__device__ float g_degw[NN];
__device__ int   g_csr_src[NE];
__device__ float g_csr_w[NE];
__device__ int   g_blocksum[512];
__device__ int   g_blockpref[512];
__device__ float g_colsum[3 * D];        // per-layer column stats (zeroed once)
__device__ float g_colsumsq[3 * D];

// ---------------- helpers -------------------------------------------------------
__device__ __forceinline__ uint32_t ph2(float a, float b) {
    __half2 h = __floats2half2_rn(a, b);
    return *(uint32_t*)&h;
}
__device__ __forceinline__ void split_half(float v, __half& hi, __half& lo) {
    hi = __float2half(v);
    lo = __float2half(v - __half2float(hi));
}
__device__ __forceinline__ uint32_t smem_u32(const void* p) {
    uint32_t a;
    asm("{ .reg .u64 t; cvta.to.shared.u64 t, %1; cvt.u32.u64 %0, t; }" : "=r"(a) : "l"(p));
    return a;
}
__device__ __forceinline__ void mma16816(float* c, uint32_t a0, uint32_t a1,
                                         uint32_t a2, uint32_t a3,
                                         uint32_t b0, uint32_t b1) {
    asm volatile(
        "mma.sync.aligned.m16n8k16.row.col.f32.f16.f16.f32 "
        "{%0,%1,%2,%3}, {%4,%5,%6,%7}, {%8,%9}, {%0,%1,%2,%3};"
        : "+f"(c[0]), "+f"(c[1]), "+f"(c[2]), "+f"(c[3])
        : "r"(a0), "r"(a1), "r"(a2), "r"(a3), "r"(b0), "r"(b1));
}
__device__ __forceinline__ void ldm_x4(uint32_t* r, uint32_t addr) {
    asm volatile("ldmatrix.sync.aligned.m8n8.x4.shared.b16 {%0,%1,%2,%3}, [%4];"
                 : "=r"(r[0]), "=r"(r[1]), "=r"(r[2]), "=r"(r[3]) : "r"(addr));
}

// ---------------- zero ----------------------------------------------------------
__global__ void zero_kernel() {
    int i = blockIdx.x * blockDim.x + threadIdx.x;
    if (i < NN) { g_counts[i] = 0; g_degw[i] = 0.f; }
    if (i < 3 * D) { g_colsum[i] = 0.f; g_colsumsq[i] = 0.f; }
}

// ---------------- degree histogram ---------------------------------------------
__global__ void hist_kernel(const int* __restrict__ col, const float* __restrict__ ew) {
    int i = blockIdx.x * blockDim.x + threadIdx.x;
    if (i < NE) {
        int c = col[i];
        atomicAdd(&g_counts[c], 1);
        atomicAdd(&g_degw[c], ew[i]);
    }
}

// ---------------- 3-phase block scan -------------------------------------------
__global__ void scan1_kernel() {
    __shared__ int wsum[8];
    int tid = threadIdx.x, lane = tid & 31, wid = tid >> 5;
    int i = blockIdx.x * 256 + tid;
    int v = (i < NN) ? g_counts[i] : 0;
    int x = v;
    #pragma unroll
    for (int o = 1; o < 32; o <<= 1) {
        int t = __shfl_up_sync(0xffffffffu, x, o);
        if (lane >= o) x += t;
    }
    if (lane == 31) wsum[wid] = x;
    __syncthreads();
    if (tid < 8) {
        int s = wsum[tid];
        #pragma unroll
        for (int o = 1; o < 8; o <<= 1) {
            int t = __shfl_up_sync(0xffu, s, o, 8);
            if (tid >= o) s += t;
        }
        wsum[tid] = s;
    }
    __syncthreads();
    int excl = (wid ? wsum[wid - 1] : 0) + x - v;
    if (i < NN) g_offsets[i] = excl;
    if (tid == 255) g_blocksum[blockIdx.x] = wsum[7];
}

__global__ void scan2_kernel(int nb) {
    __shared__ int wsum[16];
    int tid = threadIdx.x, lane = tid & 31, wid = tid >> 5;
    int v = (tid < nb) ? g_blocksum[tid] : 0;
    int x = v;
    #pragma unroll
    for (int o = 1; o < 32; o <<= 1) {
        int t = __shfl_up_sync(0xffffffffu, x, o);
        if (lane >= o) x += t;
    }
    if (lane == 31) wsum[wid] = x;
    __syncthreads();
    if (tid < 16) {
        int s = wsum[tid];
        #pragma unroll
        for (int o = 1; o < 16; o <<= 1) {
            int t = __shfl_up_sync(0xffffu, s, o, 16);
            if (tid >= o) s += t;
        }
        wsum[tid] = s;
    }
    __syncthreads();
    int excl = (wid ? wsum[wid - 1] : 0) + x - v;
    if (tid < nb) g_blockpref[tid] = excl;
}

__global__ void scan3_kernel() {
    int i = blockIdx.x * blockDim.x + threadIdx.x;
    if (i < NN) {
        int off = g_offsets[i] + g_blockpref[i >> 8];
        g_offsets[i] = off;
        g_cursor[i] = off;
    }
    if (i == 0) g_offsets[NN] = NE;
}

// ---------------- CSR scatter ---------------------------------------------------
__global__ void scatter_kernel(const int* __restrict__ row, const int* __restrict__ col,
                               const float* __restrict__ ew) {
    int i = blockIdx.x * blockDim.x + threadIdx.x;
    if (i < NE) {
        int c = col[i];
        int p = atomicAdd(&g_cursor[c], 1);
        g_csr_src[p] = row[i];
        g_csr_w[p]   = ew[i];
    }
}

// ---------------- weight convert + transpose (fp16 hi/lo) -----------------------
__global__ void wconv_kernel(const float* __restrict__ Win,
                             const float* __restrict__ Ws0, const float* __restrict__ Wn0,
                             const float* __restrict__ Ws1, const float* __restrict__ Wn1,
                             const float* __restrict__ Ws2, const float* __restrict__ Wn2) {
    int i = blockIdx.x * blockDim.x + threadIdx.x;
    if (i < D * D) {
        int n = i >> 7, k = i & 127;
        float v = Win[k * D + n];
        __half h, l; split_half(v, h, l);
        g_wtih[i] = h; g_wtil[i] = l;
        return;
    }
    int j = i - D * D;
    if (j < 3 * D * 256) {
        int l = j / (D * 256), r = j % (D * 256);
        int n = r >> 8, k = r & 255;
        const float* Ws = (l == 0) ? Ws0 : (l == 1) ? Ws1 : Ws2;
        const float* Wn = (l == 0) ? Wn0 : (l == 1) ? Wn1 : Wn2;
        float v = (k < 128) ? Ws[k * D + n] : Wn[(k - 128) * D + n];
        __half h, lo; split_half(v, h, lo);
        g_wth[j] = h; g_wtl[j] = lo;
    }
}

__global__ void bias_kernel(const float* __restrict__ bs0, const float* __restrict__ bn0,
                            const float* __restrict__ bs1, const float* __restrict__ bn1,
                            const float* __restrict__ bs2, const float* __restrict__ bn2) {
    int tid = threadIdx.x;
    int l = tid >> 7, c = tid & 127;
    const float* bs = (l == 0) ? bs0 : (l == 1) ? bs1 : bs2;
    const float* bn = (l == 0) ? bn0 : (l == 1) ? bn1 : bn2;
    g_biasc[tid] = bs[c] + bn[c];
}

// ---------------- tensor-core GEMM (fp16 2-term, M-tile 256, persistent) --------
// 148 blocks loop over tiles with grid stride; B staged ONCE per block and kept
// resident; BN stats accumulated in smem across tiles, flushed once per block.
template <int KTOT, bool RELU, bool WRITE_F16, bool STATS, bool AFP32>
__global__ void __launch_bounds__(512, 1)
gemm_mma(const float* __restrict__ Ax,
         const __half* __restrict__ A1, const __half* __restrict__ A2,
         const __half* __restrict__ Bth, const __half* __restrict__ Btl,
         const float* __restrict__ bias,
         float* __restrict__ outF, __half* __restrict__ outH,
         float* __restrict__ statS, float* __restrict__ statQ, int M) {
    constexpr int MT    = 256;           // M tile
    constexpr int BPADB = KTOT + 8;      // B row stride (halfs)
    constexpr int APAD  = 136;           // A row stride (halfs), phase-local 128 k
    constexpr int NP    = KTOT / 128;    // phases
    extern __shared__ char smem[];
    __half* Bs = (__half*)smem;                  // [2pl][128][BPADB]
    __half* As = Bs + 2 * 128 * BPADB;           // [MT][APAD]
    float* s_bias = (float*)(As + MT * APAD);
    float* s_sum = s_bias + 128;
    float* s_sq  = s_sum + 128;

    const int tid = threadIdx.x;
    const int lane = tid & 31, wid = tid >> 5;
    const int wm = wid >> 2, wn = wid & 3;
    const int qr = lane >> 2, qc = (lane & 3) * 2;
    const uint32_t sBs = smem_u32(Bs);
    const uint32_t sAs = smem_u32(As);
    const int ntiles = (M + MT - 1) / MT;

    if (tid < D) {
        s_bias[tid] = bias[tid];
        if (STATS) { s_sum[tid] = 0.f; s_sq[tid] = 0.f; }
    }

    // ---- stage ALL of B (both planes, full K) — once per block ----
    constexpr int BU4 = KTOT / 8;
    #pragma unroll
    for (int i = tid; i < 2 * 128 * BU4; i += 512) {
        int plane = i / (128 * BU4);
        int rem = i - plane * (128 * BU4);
        int r = rem / BU4;
        int j = rem - r * BU4;
        const __half* src = (plane ? Btl : Bth) + r * KTOT + j * 8;
        *(uint4*)(Bs + plane * 128 * BPADB + r * BPADB + j * 8) = *(const uint4*)src;
    }

    // ldmatrix lane-address components
    const int a_row_l = lane & 15;
    const int a_col_l = (lane >> 4) * 8;
    const int b_row_l = (lane & 7) + ((lane >> 4) << 3);
    const int b_col_l = ((lane >> 3) & 1) * 8;

    for (int tile = blockIdx.x; tile < ntiles; tile += gridDim.x) {
        const int row0 = tile * MT;
        __syncthreads();   // B visible (1st iter); As reuse safe (later iters)

        // ---- stage A phase 0 (MT x 128 fp16 = 4096 16B units, 8/thread) ----
        #pragma unroll
        for (int t = 0; t < 8; t++) {
            int u = tid + t * 512;
            int r = u >> 4, j = u & 15;
            int g = row0 + r;
            if (AFP32) {
                float4 f0 = make_float4(0.f, 0.f, 0.f, 0.f);
                float4 f1 = make_float4(0.f, 0.f, 0.f, 0.f);
                if (g < M) {
                    f0 = *(const float4*)(Ax + (size_t)g * D + j * 8);
                    f1 = *(const float4*)(Ax + (size_t)g * D + j * 8 + 4);
                }
                uint4 v = make_uint4(ph2(f0.x, f0.y), ph2(f0.z, f0.w),
                                     ph2(f1.x, f1.y), ph2(f1.z, f1.w));
                *(uint4*)(As + r * APAD + j * 8) = v;
            } else {
                uint4 v = make_uint4(0, 0, 0, 0);
                if (g < M) v = *(const uint4*)(A1 + (size_t)g * D + j * 8);
                *(uint4*)(As + r * APAD + j * 8) = v;
            }
        }
        __syncthreads();

        float acc[4][4][4];
        #pragma unroll
        for (int mi = 0; mi < 4; mi++)
            #pragma unroll
            for (int ni = 0; ni < 4; ni++)
                #pragma unroll
                for (int r = 0; r < 4; r++) acc[mi][ni][r] = 0.f;

        #pragma unroll
        for (int p = 0; p < NP; p++) {
            #pragma unroll
            for (int s = 0; s < 8; s++) {
                const int kk = s * 16;
                const int kg = p * 128 + kk;
                uint32_t ah[4][4];
                #pragma unroll
                for (int mi = 0; mi < 4; mi++) {
                    uint32_t r = wm * 64 + mi * 16 + a_row_l;
                    uint32_t c = kk + a_col_l;
                    ldm_x4(ah[mi], sAs + (r * APAD + c) * 2);
                }
                uint32_t bh[4][2], bl[4][2];
                #pragma unroll
                for (int pp = 0; pp < 2; pp++) {
                    uint32_t r = wn * 32 + pp * 16 + b_row_l;
                    uint32_t c = kg + b_col_l;
                    uint32_t t[4];
                    ldm_x4(t, sBs + (r * BPADB + c) * 2);
                    bh[pp * 2][0] = t[0]; bh[pp * 2][1] = t[1];
                    bh[pp * 2 + 1][0] = t[2]; bh[pp * 2 + 1][1] = t[3];
                    ldm_x4(t, sBs + (128 * BPADB + r * BPADB + c) * 2);
                    bl[pp * 2][0] = t[0]; bl[pp * 2][1] = t[1];
                    bl[pp * 2 + 1][0] = t[2]; bl[pp * 2 + 1][1] = t[3];
                }
                #pragma unroll
                for (int mi = 0; mi < 4; mi++) {
                    #pragma unroll
                    for (int ni = 0; ni < 4; ni++) {
                        mma16816(acc[mi][ni], ah[mi][0], ah[mi][1], ah[mi][2], ah[mi][3],
                                 bh[ni][0], bh[ni][1]);
                        mma16816(acc[mi][ni], ah[mi][0], ah[mi][1], ah[mi][2], ah[mi][3],
                                 bl[ni][0], bl[ni][1]);
                    }
                }
            }

            if (p + 1 < NP) {
                __syncthreads();
                #pragma unroll
                for (int t = 0; t < 8; t++) {     // LDG->STS phase-1 A (nb plane)
                    int u = tid + t * 512;
                    int r = u >> 4, j = u & 15;
                    int g = row0 + r;
                    uint4 v = make_uint4(0, 0, 0, 0);
                    if (g < M) v = *(const uint4*)(A2 + (size_t)g * D + j * 8);
                    *(uint4*)(As + r * APAD + j * 8) = v;
                }
                __syncthreads();
            }
        }

        // ---- epilogue: bias (+relu) (+fp16 write) (+stats into smem) ----
        float cs[8], cq[8];
        if (STATS) {
            #pragma unroll
            for (int j = 0; j < 8; j++) { cs[j] = 0.f; cq[j] = 0.f; }
        }

        #pragma unroll
        for (int mi = 0; mi < 4; mi++) {
            int r0 = row0 + wm * 64 + mi * 16 + qr;
            #pragma unroll
            for (int ni = 0; ni < 4; ni++) {
                int col = wn * 32 + ni * 8 + qc;
                float b0v = s_bias[col], b1v = s_bias[col + 1];
                float v00 = acc[mi][ni][0] + b0v, v01 = acc[mi][ni][1] + b1v;
                float v10 = acc[mi][ni][2] + b0v, v11 = acc[mi][ni][3] + b1v;
                if (RELU) {
                    v00 = fmaxf(v00, 0.f); v01 = fmaxf(v01, 0.f);
                    v10 = fmaxf(v10, 0.f); v11 = fmaxf(v11, 0.f);
                }
                if (r0 < M) {
                    *(float2*)(outF + (size_t)r0 * D + col) = make_float2(v00, v01);
                    if (STATS) {
                        cs[ni * 2] += v00; cq[ni * 2] += v00 * v00;
                        cs[ni * 2 + 1] += v01; cq[ni * 2 + 1] += v01 * v01;
                    }
                    if (WRITE_F16)
                        *(uint32_t*)(outH + (size_t)r0 * D + col) = ph2(v00, v01);
                }
                if (r0 + 8 < M) {
                    *(float2*)(outF + (size_t)(r0 + 8) * D + col) = make_float2(v10, v11);
                    if (STATS) {
                        cs[ni * 2] += v10; cq[ni * 2] += v10 * v10;
                        cs[ni * 2 + 1] += v11; cq[ni * 2 + 1] += v11 * v11;
                    }
                    if (WRITE_F16)
                        *(uint32_t*)(outH + (size_t)(r0 + 8) * D + col) = ph2(v10, v11);
                }
            }
        }

        if (STATS) {
            #pragma unroll
            for (int o = 4; o < 32; o <<= 1) {
                #pragma unroll
                for (int j = 0; j < 8; j++) {
                    cs[j] += __shfl_down_sync(0xffffffffu, cs[j], o);
                    cq[j] += __shfl_down_sync(0xffffffffu, cq[j], o);
                }
            }
            if (lane < 4) {
                #pragma unroll
                for (int ni = 0; ni < 4; ni++) {
                    int col = wn * 32 + ni * 8 + qc;
                    atomicAdd(&s_sum[col],     cs[ni * 2]);
                    atomicAdd(&s_sq[col],      cq[ni * 2]);
                    atomicAdd(&s_sum[col + 1], cs[ni * 2 + 1]);
                    atomicAdd(&s_sq[col + 1],  cq[ni * 2 + 1]);
                }
            }
        }
    }

    if (STATS) {
        __syncthreads();
        if (tid < D) {
            atomicAdd(&statS[tid], s_sum[tid]);
            atomicAdd(&statQ[tid], s_sq[tid]);
        }
    }
}

// ---------------- per-node weighted-mean aggregation (warp per node) ------------
__global__ void aggregate_kernel() {
    int warp = (blockIdx.x * blockDim.x + threadIdx.x) >> 5;
    int lane = threadIdx.x & 31;
    if (warp >= NN) return;
    int start = g_offsets[warp], end = g_offsets[warp + 1];
    float4 acc = make_float4(0.f, 0.f, 0.f, 0.f);
    for (int e = start; e < end; e += 32) {
        int idx = e + lane;
        int s = 0; float w = 0.f;
        if (idx < end) { s = g_csr_src[idx]; w = g_csr_w[idx]; }
        int cnt = min(32, end - e);
        for (int j = 0; j < cnt; j++) {
            int   sj = __shfl_sync(0xffffffffu, s, j);
            float wj = __shfl_sync(0xffffffffu, w, j);
            uint2 u = *(const uint2*)(g_ha + (size_t)sj * D + lane * 4);
            float2 f0 = __half22float2(*(__half2*)&u.x);
            float2 f1 = __half22float2(*(__half2*)&u.y);
            acc.x += f0.x * wj; acc.y += f0.y * wj;
            acc.z += f1.x * wj; acc.w += f1.y * wj;
        }
    }
    float dg = fmaxf(g_degw[warp], 1.0f);
    float inv = 1.0f / dg;
    acc.x *= inv; acc.y *= inv; acc.z *= inv; acc.w *= inv;
    *(uint2*)(g_nba + (size_t)warp * D + lane * 4) =
        make_uint2(ph2(acc.x, acc.y), ph2(acc.z, acc.w));
}

// ---------------- bn + (relu) + residual (+ fp16 plane); scale/shift inline -----
__global__ void __launch_bounds__(512)
bn_res_kernel(float* __restrict__ out, __half* __restrict__ oh,
              int relu,
              const float* __restrict__ csum,
              const float* __restrict__ csumsq,
              const float* __restrict__ gg,
              const float* __restrict__ be) {
    __shared__ float s_scale[D], s_shift[D];
    int tid = threadIdx.x;
    if (tid < D) {
        const float invn = 1.0f / (float)NN;
        float mu  = csum[tid] * invn;
        float var = csumsq[tid] * invn - mu * mu;
        var = fmaxf(var, 0.f);
        float sc = gg[tid] * rsqrtf(var + 1e-5f);
        s_scale[tid] = sc;
        s_shift[tid] = be[tid] - mu * sc;
    }
    __syncthreads();

    int i = blockIdx.x * blockDim.x + tid;
    if (i >= NN * D / 4) return;
    int cb = (i * 4) & (D - 1);
    float4 t  = ((const float4*)g_tmp)[i];
    float4 hv = ((const float4*)g_h)[i];
    float4 v;
    v.x = t.x * s_scale[cb]     + s_shift[cb];
    v.y = t.y * s_scale[cb + 1] + s_shift[cb + 1];
    v.z = t.z * s_scale[cb + 2] + s_shift[cb + 2];
    v.w = t.w * s_scale[cb + 3] + s_shift[cb + 3];
    if (relu) {
        v.x = fmaxf(v.x, 0.f); v.y = fmaxf(v.y, 0.f);
        v.z = fmaxf(v.z, 0.f); v.w = fmaxf(v.w, 0.f);
    }
    v.x += hv.x; v.y += hv.y; v.z += hv.z; v.w += hv.w;
    ((float4*)out)[i] = v;
    if (oh) {
        *(uint2*)(oh + (size_t)i * 4) = make_uint2(ph2(v.x, v.y), ph2(v.z, v.w));
    }
}

// ---------------- side stream (created at static-init time, before checkpoints) -
static cudaStream_t s_side = nullptr;
static cudaEvent_t  ev_fork = nullptr, ev_join = nullptr;
namespace {
struct SideInit {
    SideInit() {
        cudaStreamCreateWithFlags(&s_side, cudaStreamNonBlocking);
        cudaEventCreateWithFlags(&ev_fork, cudaEventDisableTiming);
        cudaEventCreateWithFlags(&ev_join, cudaEventDisableTiming);
    }
};
static SideInit g_side_init;
}

// ---------------- launch ---------------------------------------------------------
extern "C" void kernel_launch(void* const* d_in, const int* in_sizes, int n_in,
                              void* d_out, int out_size) {
    const float* x    = (const float*)d_in[0];
    const int*   ei   = (const int*)d_in[1];
    const float* ew   = (const float*)d_in[2];
    const float* W_in = (const float*)d_in[3];
    const float* b_in = (const float*)d_in[4];
    const float* P[18];
    for (int i = 0; i < 18; i++) P[i] = (const float*)d_in[5 + i];
    const int* row = ei;
    const int* col = ei + NE;
    float* out = (float*)d_out;

    float *ph, *ptmp, *pbiasc, *pcs, *pcq;
    __half *pha, *pnba, *pwth, *pwtl, *pwtih, *pwtil;
    cudaGetSymbolAddress((void**)&ph,    g_h);
    cudaGetSymbolAddress((void**)&ptmp,  g_tmp);
    cudaGetSymbolAddress((void**)&pha,   g_ha);
    cudaGetSymbolAddress((void**)&pnba,  g_nba);
    cudaGetSymbolAddress((void**)&pwth,  g_wth);
    cudaGetSymbolAddress((void**)&pwtl,  g_wtl);
    cudaGetSymbolAddress((void**)&pwtih, g_wtih);
    cudaGetSymbolAddress((void**)&pwtil, g_wtil);
    cudaGetSymbolAddress((void**)&pbiasc, g_biasc);
    cudaGetSymbolAddress((void**)&pcs,   g_colsum);
    cudaGetSymbolAddress((void**)&pcq,   g_colsumsq);

    // smem: B[2][128][KTOT+8] + A[256][136] (fp16) + bias/stats
    const int SM128 = (2 * 128 * 136 + 256 * 136) * 2 + 3 * 512;   // 140800
    const int SM256 = (2 * 128 * 264 + 256 * 136) * 2 + 3 * 512;   // 206336
    cudaFuncSetAttribute(gemm_mma<128, true,  true,  false, true>,
                         cudaFuncAttributeMaxDynamicSharedMemorySize, SM128);
    cudaFuncSetAttribute(gemm_mma<256, false, false, true,  false>,
                         cudaFuncAttributeMaxDynamicSharedMemorySize, SM256);

    const int PGRID   = 148;                  // persistent: one CTA per SM
    const int SCAN_NB = (NN + 255) / 256;     // 391

    // index 0: zeros (needed by both branches)
    zero_kernel<<<(NN + 255) / 256, 256>>>();

    // fork side stream for CSR build (falls back to serial if events fail)
    bool forked = false;
    if (s_side && ev_fork && ev_join) {
        if (cudaEventRecord(ev_fork, 0) == cudaSuccess &&
            cudaStreamWaitEvent(s_side, ev_fork, 0) == cudaSuccess)
            forked = true;
    }
    cudaStream_t cs = forked ? s_side : (cudaStream_t)0;

    // index 1..2: prerequisites for input GEMM
    wconv_kernel<<<(D * D + 3 * D * 256 + 255) / 256, 256>>>(
        W_in, P[0], P[2], P[6], P[8], P[12], P[14]);
    bias_kernel<<<1, 384>>>(P[1], P[3], P[7], P[9], P[13], P[15]);

    // index 3 (profiled): input GEMM, x->fp16 fused into staging
    gemm_mma<128, true, true, false, true><<<PGRID, 512, SM128>>>(
        x, nullptr, nullptr, pwtih, pwtil, b_in, ph, pha, nullptr, nullptr, NN);

    // CSR build on side stream (overlaps with wconv/bias/gemm_in)
    hist_kernel<<<(NE + 255) / 256, 256, 0, cs>>>(col, ew);
    scan1_kernel<<<SCAN_NB, 256, 0, cs>>>();
    scan2_kernel<<<1, 512, 0, cs>>>(SCAN_NB);
    scan3_kernel<<<SCAN_NB, 256, 0, cs>>>();
    scatter_kernel<<<(NE + 255) / 256, 256, 0, cs>>>(row, col, ew);

    if (forked) {
        cudaEventRecord(ev_join, s_side);
        cudaStreamWaitEvent((cudaStream_t)0, ev_join, 0);
    }

    for (int l = 0; l < 3; l++) {
        aggregate_kernel<<<NN / 8, 256>>>();
        gemm_mma<256, false, false, true, false><<<PGRID, 512, SM256>>>(
            nullptr, pha, pnba,
            pwth + l * D * 256, pwtl + l * D * 256, pbiasc + l * D,
            ptmp, nullptr, pcs + l * D, pcq + l * D, NN);
        bn_res_kernel<<<(NN * D / 4 + 511) / 512, 512>>>(
            (l < 2) ? ph : out,
            (l < 2) ? pha : nullptr,
            (l < 2) ? 1 : 0,
            pcs + l * D, pcq + l * D, P[6 * l + 4], P[6 * l + 5]);
    }
}

// round 17
// speedup vs baseline: 1.1657x; 1.0045x over previous
#include <cuda_runtime.h>
#include <cuda_fp16.h>
#include <cstdint>

static constexpr int NN = 100000;
static constexpr int NE = 1600000;
static constexpr int D  = 128;

// ---------------- scratch (device globals; no allocations allowed) ----------
__device__ float g_h[NN * D];
__device__ float g_tmp[NN * D];
__device__ __half g_ha[NN * D];          // h as fp16 (single plane)
__device__ __half g_nba[NN * D];         // aggregated neighbors as fp16
__device__ __half g_wth[3 * D * 256];    // layer W^T hi [l][n][k]; k<128:Ws, k>=128:Wn
__device__ __half g_wtl[3 * D * 256];    // layer W^T lo
__device__ __half g_wtih[D * D];         // input W^T hi [n][k]
__device__ __half g_wtil[D * D];         // input W^T lo
__device__ float g_biasc[3 * D];
__device__ int   g_counts[NN];
__device__ int   g_offsets[NN + 1];
__device__ int   g_cursor[NN];
__device__ int   g_csr_src[NE];
__device__ float g_csr_w[NE];
__device__ int   g_blocksum[512];
__device__ int   g_blockpref[512];
__device__ float g_colsum[3 * D];        // per-layer column stats (zeroed once)
__device__ float g_colsumsq[3 * D];

// ---------------- helpers -------------------------------------------------------
__device__ __forceinline__ uint32_t ph2(float a, float b) {
    __half2 h = __floats2half2_rn(a, b);
    return *(uint32_t*)&h;
}
__device__ __forceinline__ void split_half(float v, __half& hi, __half& lo) {
    hi = __float2half(v);
    lo = __float2half(v - __half2float(hi));
}
__device__ __forceinline__ uint32_t smem_u32(const void* p) {
    uint32_t a;
    asm("{ .reg .u64 t; cvta.to.shared.u64 t, %1; cvt.u32.u64 %0, t; }" : "=r"(a) : "l"(p));
    return a;
}
__device__ __forceinline__ void mma16816(float* c, uint32_t a0, uint32_t a1,
                                         uint32_t a2, uint32_t a3,
                                         uint32_t b0, uint32_t b1) {
    asm volatile(
        "mma.sync.aligned.m16n8k16.row.col.f32.f16.f16.f32 "
        "{%0,%1,%2,%3}, {%4,%5,%6,%7}, {%8,%9}, {%0,%1,%2,%3};"
        : "+f"(c[0]), "+f"(c[1]), "+f"(c[2]), "+f"(c[3])
        : "r"(a0), "r"(a1), "r"(a2), "r"(a3), "r"(b0), "r"(b1));
}
__device__ __forceinline__ void ldm_x4(uint32_t* r, uint32_t addr) {
    asm volatile("ldmatrix.sync.aligned.m8n8.x4.shared.b16 {%0,%1,%2,%3}, [%4];"
                 : "=r"(r[0]), "=r"(r[1]), "=r"(r[2]), "=r"(r[3]) : "r"(addr));
}

// ---------------- zero ----------------------------------------------------------
__global__ void zero_kernel() {
    int i = blockIdx.x * blockDim.x + threadIdx.x;
    if (i < NN) g_counts[i] = 0;
    if (i < 3 * D) { g_colsum[i] = 0.f; g_colsumsq[i] = 0.f; }
}

// ---------------- degree histogram (count only; degw computed in aggregate) -----
__global__ void hist_kernel(const int* __restrict__ col) {
    int i = blockIdx.x * blockDim.x + threadIdx.x;
    if (i < NE) atomicAdd(&g_counts[col[i]], 1);
}

// ---------------- 3-phase block scan -------------------------------------------
__global__ void scan1_kernel() {
    __shared__ int wsum[8];
    int tid = threadIdx.x, lane = tid & 31, wid = tid >> 5;
    int i = blockIdx.x * 256 + tid;
    int v = (i < NN) ? g_counts[i] : 0;
    int x = v;
    #pragma unroll
    for (int o = 1; o < 32; o <<= 1) {
        int t = __shfl_up_sync(0xffffffffu, x, o);
        if (lane >= o) x += t;
    }
    if (lane == 31) wsum[wid] = x;
    __syncthreads();
    if (tid < 8) {
        int s = wsum[tid];
        #pragma unroll
        for (int o = 1; o < 8; o <<= 1) {
            int t = __shfl_up_sync(0xffu, s, o, 8);
            if (tid >= o) s += t;
        }
        wsum[tid] = s;
    }
    __syncthreads();
    int excl = (wid ? wsum[wid - 1] : 0) + x - v;
    if (i < NN) g_offsets[i] = excl;
    if (tid == 255) g_blocksum[blockIdx.x] = wsum[7];
}

__global__ void scan2_kernel(int nb) {
    __shared__ int wsum[16];
    int tid = threadIdx.x, lane = tid & 31, wid = tid >> 5;
    int v = (tid < nb) ? g_blocksum[tid] : 0;
    int x = v;
    #pragma unroll
    for (int o = 1; o < 32; o <<= 1) {
        int t = __shfl_up_sync(0xffffffffu, x, o);
        if (lane >= o) x += t;
    }
    if (lane == 31) wsum[wid] = x;
    __syncthreads();
    if (tid < 16) {
        int s = wsum[tid];
        #pragma unroll
        for (int o = 1; o < 16; o <<= 1) {
            int t = __shfl_up_sync(0xffffu, s, o, 16);
            if (tid >= o) s += t;
        }
        wsum[tid] = s;
    }
    __syncthreads();
    int excl = (wid ? wsum[wid - 1] : 0) + x - v;
    if (tid < nb) g_blockpref[tid] = excl;
}

__global__ void scan3_kernel() {
    int i = blockIdx.x * blockDim.x + threadIdx.x;
    if (i < NN) {
        int off = g_offsets[i] + g_blockpref[i >> 8];
        g_offsets[i] = off;
        g_cursor[i] = off;
    }
    if (i == 0) g_offsets[NN] = NE;
}

// ---------------- CSR scatter ---------------------------------------------------
__global__ void scatter_kernel(const int* __restrict__ row, const int* __restrict__ col,
                               const float* __restrict__ ew) {
    int i = blockIdx.x * blockDim.x + threadIdx.x;
    if (i < NE) {
        int c = col[i];
        int p = atomicAdd(&g_cursor[c], 1);
        g_csr_src[p] = row[i];
        g_csr_w[p]   = ew[i];
    }
}

// ---------------- weight convert + transpose (fp16 hi/lo) -----------------------
__global__ void wconv_kernel(const float* __restrict__ Win,
                             const float* __restrict__ Ws0, const float* __restrict__ Wn0,
                             const float* __restrict__ Ws1, const float* __restrict__ Wn1,
                             const float* __restrict__ Ws2, const float* __restrict__ Wn2) {
    int i = blockIdx.x * blockDim.x + threadIdx.x;
    if (i < D * D) {
        int n = i >> 7, k = i & 127;
        float v = Win[k * D + n];
        __half h, l; split_half(v, h, l);
        g_wtih[i] = h; g_wtil[i] = l;
        return;
    }
    int j = i - D * D;
    if (j < 3 * D * 256) {
        int l = j / (D * 256), r = j % (D * 256);
        int n = r >> 8, k = r & 255;
        const float* Ws = (l == 0) ? Ws0 : (l == 1) ? Ws1 : Ws2;
        const float* Wn = (l == 0) ? Wn0 : (l == 1) ? Wn1 : Wn2;
        float v = (k < 128) ? Ws[k * D + n] : Wn[(k - 128) * D + n];
        __half h, lo; split_half(v, h, lo);
        g_wth[j] = h; g_wtl[j] = lo;
    }
}

__global__ void bias_kernel(const float* __restrict__ bs0, const float* __restrict__ bn0,
                            const float* __restrict__ bs1, const float* __restrict__ bn1,
                            const float* __restrict__ bs2, const float* __restrict__ bn2) {
    int tid = threadIdx.x;
    int l = tid >> 7, c = tid & 127;
    const float* bs = (l == 0) ? bs0 : (l == 1) ? bs1 : bs2;
    const float* bn = (l == 0) ? bn0 : (l == 1) ? bn1 : bn2;
    g_biasc[tid] = bs[c] + bn[c];
}

// ---------------- tensor-core GEMM (fp16 2-term, M-tile 256, persistent) --------
// 148 blocks loop over tiles with grid stride; B staged ONCE per block and kept
// resident; BN stats accumulated in smem across tiles, flushed once per block.
template <int KTOT, bool RELU, bool WRITE_F16, bool STATS, bool AFP32>
__global__ void __launch_bounds__(512, 1)
gemm_mma(const float* __restrict__ Ax,
         const __half* __restrict__ A1, const __half* __restrict__ A2,
         const __half* __restrict__ Bth, const __half* __restrict__ Btl,
         const float* __restrict__ bias,
         float* __restrict__ outF, __half* __restrict__ outH,
         float* __restrict__ statS, float* __restrict__ statQ, int M) {
    constexpr int MT    = 256;           // M tile
    constexpr int BPADB = KTOT + 8;      // B row stride (halfs)
    constexpr int APAD  = 136;           // A row stride (halfs), phase-local 128 k
    constexpr int NP    = KTOT / 128;    // phases
    extern __shared__ char smem[];
    __half* Bs = (__half*)smem;                  // [2pl][128][BPADB]
    __half* As = Bs + 2 * 128 * BPADB;           // [MT][APAD]
    float* s_bias = (float*)(As + MT * APAD);
    float* s_sum = s_bias + 128;
    float* s_sq  = s_sum + 128;

    const int tid = threadIdx.x;
    const int lane = tid & 31, wid = tid >> 5;
    const int wm = wid >> 2, wn = wid & 3;
    const int qr = lane >> 2, qc = (lane & 3) * 2;
    const uint32_t sBs = smem_u32(Bs);
    const uint32_t sAs = smem_u32(As);
    const int ntiles = (M + MT - 1) / MT;

    if (tid < D) {
        s_bias[tid] = bias[tid];
        if (STATS) { s_sum[tid] = 0.f; s_sq[tid] = 0.f; }
    }

    // ---- stage ALL of B (both planes, full K) — once per block ----
    constexpr int BU4 = KTOT / 8;
    #pragma unroll
    for (int i = tid; i < 2 * 128 * BU4; i += 512) {
        int plane = i / (128 * BU4);
        int rem = i - plane * (128 * BU4);
        int r = rem / BU4;
        int j = rem - r * BU4;
        const __half* src = (plane ? Btl : Bth) + r * KTOT + j * 8;
        *(uint4*)(Bs + plane * 128 * BPADB + r * BPADB + j * 8) = *(const uint4*)src;
    }

    // ldmatrix lane-address components
    const int a_row_l = lane & 15;
    const int a_col_l = (lane >> 4) * 8;
    const int b_row_l = (lane & 7) + ((lane >> 4) << 3);
    const int b_col_l = ((lane >> 3) & 1) * 8;

    for (int tile = blockIdx.x; tile < ntiles; tile += gridDim.x) {
        const int row0 = tile * MT;
        __syncthreads();   // B visible (1st iter); As reuse safe (later iters)

        // ---- stage A phase 0 (MT x 128 fp16 = 4096 16B units, 8/thread) ----
        #pragma unroll
        for (int t = 0; t < 8; t++) {
            int u = tid + t * 512;
            int r = u >> 4, j = u & 15;
            int g = row0 + r;
            if (AFP32) {
                float4 f0 = make_float4(0.f, 0.f, 0.f, 0.f);
                float4 f1 = make_float4(0.f, 0.f, 0.f, 0.f);
                if (g < M) {
                    f0 = *(const float4*)(Ax + (size_t)g * D + j * 8);
                    f1 = *(const float4*)(Ax + (size_t)g * D + j * 8 + 4);
                }
                uint4 v = make_uint4(ph2(f0.x, f0.y), ph2(f0.z, f0.w),
                                     ph2(f1.x, f1.y), ph2(f1.z, f1.w));
                *(uint4*)(As + r * APAD + j * 8) = v;
            } else {
                uint4 v = make_uint4(0, 0, 0, 0);
                if (g < M) v = *(const uint4*)(A1 + (size_t)g * D + j * 8);
                *(uint4*)(As + r * APAD + j * 8) = v;
            }
        }
        __syncthreads();

        float acc[4][4][4];
        #pragma unroll
        for (int mi = 0; mi < 4; mi++)
            #pragma unroll
            for (int ni = 0; ni < 4; ni++)
                #pragma unroll
                for (int r = 0; r < 4; r++) acc[mi][ni][r] = 0.f;

        #pragma unroll
        for (int p = 0; p < NP; p++) {
            #pragma unroll
            for (int s = 0; s < 8; s++) {
                const int kk = s * 16;
                const int kg = p * 128 + kk;
                uint32_t ah[4][4];
                #pragma unroll
                for (int mi = 0; mi < 4; mi++) {
                    uint32_t r = wm * 64 + mi * 16 + a_row_l;
                    uint32_t c = kk + a_col_l;
                    ldm_x4(ah[mi], sAs + (r * APAD + c) * 2);
                }
                uint32_t bh[4][2], bl[4][2];
                #pragma unroll
                for (int pp = 0; pp < 2; pp++) {
                    uint32_t r = wn * 32 + pp * 16 + b_row_l;
                    uint32_t c = kg + b_col_l;
                    uint32_t t[4];
                    ldm_x4(t, sBs + (r * BPADB + c) * 2);
                    bh[pp * 2][0] = t[0]; bh[pp * 2][1] = t[1];
                    bh[pp * 2 + 1][0] = t[2]; bh[pp * 2 + 1][1] = t[3];
                    ldm_x4(t, sBs + (128 * BPADB + r * BPADB + c) * 2);
                    bl[pp * 2][0] = t[0]; bl[pp * 2][1] = t[1];
                    bl[pp * 2 + 1][0] = t[2]; bl[pp * 2 + 1][1] = t[3];
                }
                #pragma unroll
                for (int mi = 0; mi < 4; mi++) {
                    #pragma unroll
                    for (int ni = 0; ni < 4; ni++) {
                        mma16816(acc[mi][ni], ah[mi][0], ah[mi][1], ah[mi][2], ah[mi][3],
                                 bh[ni][0], bh[ni][1]);
                        mma16816(acc[mi][ni], ah[mi][0], ah[mi][1], ah[mi][2], ah[mi][3],
                                 bl[ni][0], bl[ni][1]);
                    }
                }
            }

            if (p + 1 < NP) {
                __syncthreads();
                #pragma unroll
                for (int t = 0; t < 8; t++) {     // LDG->STS phase-1 A (nb plane)
                    int u = tid + t * 512;
                    int r = u >> 4, j = u & 15;
                    int g = row0 + r;
                    uint4 v = make_uint4(0, 0, 0, 0);
                    if (g < M) v = *(const uint4*)(A2 + (size_t)g * D + j * 8);
                    *(uint4*)(As + r * APAD + j * 8) = v;
                }
                __syncthreads();
            }
        }

        // ---- epilogue: bias (+relu) (+fp16 write) (+stats into smem) ----
        float cs[8], cq[8];
        if (STATS) {
            #pragma unroll
            for (int j = 0; j < 8; j++) { cs[j] = 0.f; cq[j] = 0.f; }
        }

        #pragma unroll
        for (int mi = 0; mi < 4; mi++) {
            int r0 = row0 + wm * 64 + mi * 16 + qr;
            #pragma unroll
            for (int ni = 0; ni < 4; ni++) {
                int col = wn * 32 + ni * 8 + qc;
                float b0v = s_bias[col], b1v = s_bias[col + 1];
                float v00 = acc[mi][ni][0] + b0v, v01 = acc[mi][ni][1] + b1v;
                float v10 = acc[mi][ni][2] + b0v, v11 = acc[mi][ni][3] + b1v;
                if (RELU) {
                    v00 = fmaxf(v00, 0.f); v01 = fmaxf(v01, 0.f);
                    v10 = fmaxf(v10, 0.f); v11 = fmaxf(v11, 0.f);
                }
                if (r0 < M) {
                    *(float2*)(outF + (size_t)r0 * D + col) = make_float2(v00, v01);
                    if (STATS) {
                        cs[ni * 2] += v00; cq[ni * 2] += v00 * v00;
                        cs[ni * 2 + 1] += v01; cq[ni * 2 + 1] += v01 * v01;
                    }
                    if (WRITE_F16)
                        *(uint32_t*)(outH + (size_t)r0 * D + col) = ph2(v00, v01);
                }
                if (r0 + 8 < M) {
                    *(float2*)(outF + (size_t)(r0 + 8) * D + col) = make_float2(v10, v11);
                    if (STATS) {
                        cs[ni * 2] += v10; cq[ni * 2] += v10 * v10;
                        cs[ni * 2 + 1] += v11; cq[ni * 2 + 1] += v11 * v11;
                    }
                    if (WRITE_F16)
                        *(uint32_t*)(outH + (size_t)(r0 + 8) * D + col) = ph2(v10, v11);
                }
            }
        }

        if (STATS) {
            #pragma unroll
            for (int o = 4; o < 32; o <<= 1) {
                #pragma unroll
                for (int j = 0; j < 8; j++) {
                    cs[j] += __shfl_down_sync(0xffffffffu, cs[j], o);
                    cq[j] += __shfl_down_sync(0xffffffffu, cq[j], o);
                }
            }
            if (lane < 4) {
                #pragma unroll
                for (int ni = 0; ni < 4; ni++) {
                    int col = wn * 32 + ni * 8 + qc;
                    atomicAdd(&s_sum[col],     cs[ni * 2]);
                    atomicAdd(&s_sq[col],      cq[ni * 2]);
                    atomicAdd(&s_sum[col + 1], cs[ni * 2 + 1]);
                    atomicAdd(&s_sq[col + 1],  cq[ni * 2 + 1]);
                }
            }
        }
    }

    if (STATS) {
        __syncthreads();
        if (tid < D) {
            atomicAdd(&statS[tid], s_sum[tid]);
            atomicAdd(&statQ[tid], s_sq[tid]);
        }
    }
}

// ---------------- per-node weighted-mean aggregation (warp per node) ------------
// Weighted degree computed inline from the broadcast weights (g_degw removed).
__global__ void aggregate_kernel() {
    int warp = (blockIdx.x * blockDim.x + threadIdx.x) >> 5;
    int lane = threadIdx.x & 31;
    if (warp >= NN) return;
    int start = g_offsets[warp], end = g_offsets[warp + 1];
    float4 acc = make_float4(0.f, 0.f, 0.f, 0.f);
    float wsum = 0.f;
    for (int e = start; e < end; e += 32) {
        int idx = e + lane;
        int s = 0; float w = 0.f;
        if (idx < end) { s = g_csr_src[idx]; w = g_csr_w[idx]; }
        int cnt = min(32, end - e);
        for (int j = 0; j < cnt; j++) {
            int   sj = __shfl_sync(0xffffffffu, s, j);
            float wj = __shfl_sync(0xffffffffu, w, j);
            wsum += wj;
            uint2 u = *(const uint2*)(g_ha + (size_t)sj * D + lane * 4);
            float2 f0 = __half22float2(*(__half2*)&u.x);
            float2 f1 = __half22float2(*(__half2*)&u.y);
            acc.x += f0.x * wj; acc.y += f0.y * wj;
            acc.z += f1.x * wj; acc.w += f1.y * wj;
        }
    }
    float dg = fmaxf(wsum, 1.0f);
    float inv = 1.0f / dg;
    acc.x *= inv; acc.y *= inv; acc.z *= inv; acc.w *= inv;
    *(uint2*)(g_nba + (size_t)warp * D + lane * 4) =
        make_uint2(ph2(acc.x, acc.y), ph2(acc.z, acc.w));
}

// ---------------- bn + (relu) + residual (+ fp16 plane); scale/shift inline -----
__global__ void bn_res_kernel(float* __restrict__ out, __half* __restrict__ oh,
                              int relu,
                              const float* __restrict__ csum,
                              const float* __restrict__ csumsq,
                              const float* __restrict__ gg,
                              const float* __restrict__ be) {
    __shared__ float s_scale[D], s_shift[D];
    int tid = threadIdx.x;
    if (tid < D) {
        const float invn = 1.0f / (float)NN;
        float mu  = csum[tid] * invn;
        float var = csumsq[tid] * invn - mu * mu;
        var = fmaxf(var, 0.f);
        float sc = gg[tid] * rsqrtf(var + 1e-5f);
        s_scale[tid] = sc;
        s_shift[tid] = be[tid] - mu * sc;
    }
    __syncthreads();

    int i = blockIdx.x * blockDim.x + tid;
    if (i >= NN * D / 4) return;
    int cb = (i * 4) & (D - 1);
    float4 t  = ((const float4*)g_tmp)[i];
    float4 hv = ((const float4*)g_h)[i];
    float4 v;
    v.x = t.x * s_scale[cb]     + s_shift[cb];
    v.y = t.y * s_scale[cb + 1] + s_shift[cb + 1];
    v.z = t.z * s_scale[cb + 2] + s_shift[cb + 2];
    v.w = t.w * s_scale[cb + 3] + s_shift[cb + 3];
    if (relu) {
        v.x = fmaxf(v.x, 0.f); v.y = fmaxf(v.y, 0.f);
        v.z = fmaxf(v.z, 0.f); v.w = fmaxf(v.w, 0.f);
    }
    v.x += hv.x; v.y += hv.y; v.z += hv.z; v.w += hv.w;
    ((float4*)out)[i] = v;
    if (oh) {
        *(uint2*)(oh + (size_t)i * 4) = make_uint2(ph2(v.x, v.y), ph2(v.z, v.w));
    }
}

// ---------------- side stream (created at static-init time, before checkpoints) -
static cudaStream_t s_side = nullptr;
static cudaEvent_t  ev_fork = nullptr, ev_join = nullptr;
namespace {
struct SideInit {
    SideInit() {
        cudaStreamCreateWithFlags(&s_side, cudaStreamNonBlocking);
        cudaEventCreateWithFlags(&ev_fork, cudaEventDisableTiming);
        cudaEventCreateWithFlags(&ev_join, cudaEventDisableTiming);
    }
};
static SideInit g_side_init;
}

// ---------------- launch ---------------------------------------------------------
extern "C" void kernel_launch(void* const* d_in, const int* in_sizes, int n_in,
                              void* d_out, int out_size) {
    const float* x    = (const float*)d_in[0];
    const int*   ei   = (const int*)d_in[1];
    const float* ew   = (const float*)d_in[2];
    const float* W_in = (const float*)d_in[3];
    const float* b_in = (const float*)d_in[4];
    const float* P[18];
    for (int i = 0; i < 18; i++) P[i] = (const float*)d_in[5 + i];
    const int* row = ei;
    const int* col = ei + NE;
    float* out = (float*)d_out;

    float *ph, *ptmp, *pbiasc, *pcs, *pcq;
    __half *pha, *pnba, *pwth, *pwtl, *pwtih, *pwtil;
    cudaGetSymbolAddress((void**)&ph,    g_h);
    cudaGetSymbolAddress((void**)&ptmp,  g_tmp);
    cudaGetSymbolAddress((void**)&pha,   g_ha);
    cudaGetSymbolAddress((void**)&pnba,  g_nba);
    cudaGetSymbolAddress((void**)&pwth,  g_wth);
    cudaGetSymbolAddress((void**)&pwtl,  g_wtl);
    cudaGetSymbolAddress((void**)&pwtih, g_wtih);
    cudaGetSymbolAddress((void**)&pwtil, g_wtil);
    cudaGetSymbolAddress((void**)&pbiasc, g_biasc);
    cudaGetSymbolAddress((void**)&pcs,   g_colsum);
    cudaGetSymbolAddress((void**)&pcq,   g_colsumsq);

    // smem: B[2][128][KTOT+8] + A[256][136] (fp16) + bias/stats
    const int SM128 = (2 * 128 * 136 + 256 * 136) * 2 + 3 * 512;   // 140800
    const int SM256 = (2 * 128 * 264 + 256 * 136) * 2 + 3 * 512;   // 206336
    cudaFuncSetAttribute(gemm_mma<128, true,  true,  false, true>,
                         cudaFuncAttributeMaxDynamicSharedMemorySize, SM128);
    cudaFuncSetAttribute(gemm_mma<256, false, false, true,  false>,
                         cudaFuncAttributeMaxDynamicSharedMemorySize, SM256);

    const int PGRID   = 148;                  // persistent: one CTA per SM
    const int SCAN_NB = (NN + 255) / 256;     // 391

    // index 0: zeros (needed by both branches)
    zero_kernel<<<(NN + 255) / 256, 256>>>();

    // fork side stream for CSR build (falls back to serial if events fail)
    bool forked = false;
    if (s_side && ev_fork && ev_join) {
        if (cudaEventRecord(ev_fork, 0) == cudaSuccess &&
            cudaStreamWaitEvent(s_side, ev_fork, 0) == cudaSuccess)
            forked = true;
    }
    cudaStream_t cs = forked ? s_side : (cudaStream_t)0;

    // index 1..2: prerequisites for input GEMM
    wconv_kernel<<<(D * D + 3 * D * 256 + 255) / 256, 256>>>(
        W_in, P[0], P[2], P[6], P[8], P[12], P[14]);
    bias_kernel<<<1, 384>>>(P[1], P[3], P[7], P[9], P[13], P[15]);

    // index 3 (profiled): input GEMM, x->fp16 fused into staging
    gemm_mma<128, true, true, false, true><<<PGRID, 512, SM128>>>(
        x, nullptr, nullptr, pwtih, pwtil, b_in, ph, pha, nullptr, nullptr, NN);

    // CSR build on side stream (overlaps with wconv/bias/gemm_in)
    hist_kernel<<<(NE + 255) / 256, 256, 0, cs>>>(col);
    scan1_kernel<<<SCAN_NB, 256, 0, cs>>>();
    scan2_kernel<<<1, 512, 0, cs>>>(SCAN_NB);
    scan3_kernel<<<SCAN_NB, 256, 0, cs>>>();
    scatter_kernel<<<(NE + 255) / 256, 256, 0, cs>>>(row, col, ew);

    if (forked) {
        cudaEventRecord(ev_join, s_side);
        cudaStreamWaitEvent((cudaStream_t)0, ev_join, 0);
    }

    for (int l = 0; l < 3; l++) {
        aggregate_kernel<<<NN / 8, 256>>>();
        gemm_mma<256, false, false, true, false><<<PGRID, 512, SM256>>>(
            nullptr, pha, pnba,
            pwth + l * D * 256, pwtl + l * D * 256, pbiasc + l * D,
            ptmp, nullptr, pcs + l * D, pcq + l * D, NN);
        bn_res_kernel<<<(NN * D / 4 + 255) / 256, 256>>>(
            (l < 2) ? ph : out,
            (l < 2) ? pha : nullptr,
            (l < 2) ? 1 : 0,
            pcs + l * D, pcq + l * D, P[6 * l + 4], P[6 * l + 5]);
    }
}